// round 5
// baseline (speedup 1.0000x reference)
#include <cuda_runtime.h>
#include <cstdint>

// Problem constants
#define BB   2
#define TT   2048
#define DD   1024
#define HH   16
#define HDD  64
#define MROWS (BB * TT)   // 4096

// Device scratch (no runtime allocation allowed)
__device__ float g_q[BB * HH * TT * HDD];     // [B,H,T,HD], tf32-rounded
__device__ float g_k[BB * HH * TT * HDD];
__device__ float g_v[BB * HH * TT * HDD];
__device__ float g_att[BB * TT * DD];         // [B,T,DIM], full fp32

// ---------------------------------------------------------------------------
// helpers
// ---------------------------------------------------------------------------
__device__ __forceinline__ uint32_t f2tf32(float f) {
    uint32_t r;
    asm("cvt.rna.tf32.f32 %0, %1;" : "=r"(r) : "f"(f));
    return r;
}

__device__ __forceinline__ void mma_tf32(float* c, const uint32_t* a, const uint32_t* b) {
    asm volatile(
        "mma.sync.aligned.m16n8k8.row.col.f32.tf32.tf32.f32 "
        "{%0,%1,%2,%3}, {%4,%5,%6,%7}, {%8,%9}, {%0,%1,%2,%3};"
        : "+f"(c[0]), "+f"(c[1]), "+f"(c[2]), "+f"(c[3])
        : "r"(a[0]), "r"(a[1]), "r"(a[2]), "r"(a[3]), "r"(b[0]), "r"(b[1]));
}

__device__ __forceinline__ uint32_t sptr(const void* p) {
    return (uint32_t)__cvta_generic_to_shared(p);
}

__device__ __forceinline__ void ldsm_x4(uint32_t* r, uint32_t addr) {
    asm volatile("ldmatrix.sync.aligned.m8n8.x4.shared.b16 {%0,%1,%2,%3}, [%4];"
                 : "=r"(r[0]), "=r"(r[1]), "=r"(r[2]), "=r"(r[3]) : "r"(addr));
}

// ---------------------------------------------------------------------------
// Tensor-core NT GEMM: out[m,n] = sum_k A[m,k] * W[n,k]
// CTA 128x128, BK=32, 256 threads, warp tile 32x64.
// Fragments via ldmatrix.x4 (b16 trick for tf32), staging via packed STS.128.
// QKV==1: scatter into [B,H,T,HD] with tf32 rounding (consumed by attention).
// ---------------------------------------------------------------------------
#define SA 36   // padded stride in words; 36*4 bytes = 16B-aligned rows

template <int QKV>
__device__ __forceinline__ void gemm_tc_body(const float* __restrict__ A,
                                             const float* __restrict__ W,
                                             float* __restrict__ dst)
{
    __shared__ __align__(16) uint32_t As[128 * SA];
    __shared__ __align__(16) uint32_t Bs[128 * SA];

    const int tid    = threadIdx.x;
    const int lane   = tid & 31;
    const int wid    = tid >> 5;
    const int warp_m = wid & 3;
    const int warp_n = wid >> 2;
    const int g      = lane >> 2;
    const int t4     = lane & 3;
    const int i8     = lane >> 3;   // matrix index within ldmatrix.x4
    const int rr     = lane & 7;

    const int m0 = blockIdx.y * 128;
    const int n0 = blockIdx.x * 128;

    const int lr = tid >> 3;
    const int lc = (tid & 7) << 2;

    // ldmatrix base addresses (byte addrs into shared space)
    uint32_t aAddr[2], bAddr[4];
#pragma unroll
    for (int mt = 0; mt < 2; ++mt)
        aAddr[mt] = sptr(As) +
            (((warp_m * 32 + mt * 16 + (i8 & 1) * 8 + rr) * SA + (i8 >> 1) * 4) << 2);
#pragma unroll
    for (int p = 0; p < 4; ++p)
        bAddr[p] = sptr(Bs) +
            (((warp_n * 64 + (2 * p + (i8 >> 1)) * 8 + rr) * SA + (i8 & 1) * 4) << 2);

    float acc[2][8][4];
#pragma unroll
    for (int mt = 0; mt < 2; ++mt)
#pragma unroll
        for (int nt = 0; nt < 8; ++nt)
#pragma unroll
            for (int i = 0; i < 4; ++i) acc[mt][nt][i] = 0.0f;

    float4 areg[4], breg[4];
#pragma unroll
    for (int i = 0; i < 4; ++i) {
        areg[i] = *(const float4*)(A + (size_t)(m0 + lr + 32 * i) * DD + lc);
        breg[i] = *(const float4*)(W + (size_t)(n0 + lr + 32 * i) * DD + lc);
    }

    for (int k0 = 0; k0 < DD; k0 += 32) {
        // stage regs -> smem (tf32 convert), packed 128-bit stores
#pragma unroll
        for (int i = 0; i < 4; ++i) {
            const int r = lr + 32 * i;
            uint4 pa, pb;
            pa.x = f2tf32(areg[i].x); pa.y = f2tf32(areg[i].y);
            pa.z = f2tf32(areg[i].z); pa.w = f2tf32(areg[i].w);
            pb.x = f2tf32(breg[i].x); pb.y = f2tf32(breg[i].y);
            pb.z = f2tf32(breg[i].z); pb.w = f2tf32(breg[i].w);
            *(uint4*)&As[r * SA + lc] = pa;
            *(uint4*)&Bs[r * SA + lc] = pb;
        }
        __syncthreads();

        if (k0 + 32 < DD) {
#pragma unroll
            for (int i = 0; i < 4; ++i) {
                areg[i] = *(const float4*)(A + (size_t)(m0 + lr + 32 * i) * DD + k0 + 32 + lc);
                breg[i] = *(const float4*)(W + (size_t)(n0 + lr + 32 * i) * DD + k0 + 32 + lc);
            }
        }

#pragma unroll
        for (int kk = 0; kk < 4; ++kk) {
            const uint32_t koff = kk * 32;   // 8 words * 4 bytes
            uint32_t af[2][4], bf[4][4];
#pragma unroll
            for (int mt = 0; mt < 2; ++mt) ldsm_x4(af[mt], aAddr[mt] + koff);
#pragma unroll
            for (int p = 0; p < 4; ++p) ldsm_x4(bf[p], bAddr[p] + koff);
#pragma unroll
            for (int mt = 0; mt < 2; ++mt)
#pragma unroll
                for (int nt = 0; nt < 8; ++nt)
                    mma_tf32(acc[mt][nt], af[mt], &bf[nt >> 1][(nt & 1) * 2]);
        }
        __syncthreads();
    }

    // epilogue
#pragma unroll
    for (int mt = 0; mt < 2; ++mt) {
#pragma unroll
        for (int nt = 0; nt < 8; ++nt) {
            const int m1 = m0 + warp_m * 32 + mt * 16 + g;
            const int m2 = m1 + 8;
            const int n  = n0 + warp_n * 64 + nt * 8 + t4 * 2;
            if (QKV) {
                // round to tf32 here so attention can consume raw bits
                float2 lo = make_float2(__uint_as_float(f2tf32(acc[mt][nt][0])),
                                        __uint_as_float(f2tf32(acc[mt][nt][1])));
                float2 hi = make_float2(__uint_as_float(f2tf32(acc[mt][nt][2])),
                                        __uint_as_float(f2tf32(acc[mt][nt][3])));
                const int h = n / HDD, d = n % HDD;
                const int b1 = m1 / TT, t1 = m1 % TT;
                const int b2 = m2 / TT, t2 = m2 % TT;
                *(float2*)(dst + (((size_t)(b1 * HH + h) * TT + t1) * HDD + d)) = lo;
                *(float2*)(dst + (((size_t)(b2 * HH + h) * TT + t2) * HDD + d)) = hi;
            } else {
                float2 lo = make_float2(acc[mt][nt][0], acc[mt][nt][1]);
                float2 hi = make_float2(acc[mt][nt][2], acc[mt][nt][3]);
                *(float2*)(dst + (size_t)m1 * DD + n) = lo;
                *(float2*)(dst + (size_t)m2 * DD + n) = hi;
            }
        }
    }
}

__global__ void __launch_bounds__(256)
gemm_qkv_kernel(const float* __restrict__ x,
                const float* __restrict__ wq,
                const float* __restrict__ wk,
                const float* __restrict__ wv)
{
    const float* W = (blockIdx.z == 0) ? wq : ((blockIdx.z == 1) ? wk : wv);
    float* dst     = (blockIdx.z == 0) ? g_q : ((blockIdx.z == 1) ? g_k : g_v);
    gemm_tc_body<1>(x, W, dst);
}

__global__ void __launch_bounds__(256)
gemm_out_kernel(const float* __restrict__ wo, float* __restrict__ out)
{
    gemm_tc_body<0>(g_att, wo, out);
}

// ---------------------------------------------------------------------------
// Tensor-core flash attention (tf32 MMA, fp32 softmax/accum, causal).
// CTA = (b, h, 128-row q tile), 256 threads = 8 warps, warp = 16 q rows.
// kv tiles of 64. Q fragments register-resident. V transposed in smem.
// ---------------------------------------------------------------------------
#define AS 68   // smem stride in words (16B-aligned rows)

__global__ void __launch_bounds__(256) attn_kernel()
{
    extern __shared__ float sm[];
    float* Ps = sm;                 // 128 x AS : Q staging, then P tiles
    float* Ks = sm + 128 * AS;      // 64 x AS
    float* Vt = Ks + 64 * AS;       // 64 x AS  (rows = hd, cols = kv)

    const int tid  = threadIdx.x;
    const int lane = tid & 31;
    const int w    = tid >> 5;       // warp 0..7
    const int g    = lane >> 2;      // 0..7
    const int t4   = lane & 3;       // 0..3
    const int i8   = lane >> 3;
    const int rr   = lane & 7;

    const int qt = blockIdx.x;       // 0..15
    const int hh = blockIdx.y;
    const int bb = blockIdx.z;
    const int q0 = qt * 128;

    const size_t bh_off = (size_t)(bb * HH + hh) * TT * HDD;
    const float* Qg = g_q + bh_off;
    const float* Kg = g_k + bh_off;
    const float* Vg = g_v + bh_off;

    // ---- load Q tile (128 x 64) into Ps ----
#pragma unroll
    for (int i = 0; i < 8; ++i) {
        int idx = tid + 256 * i;
        int r = idx >> 4, c = (idx & 15) << 2;
        *(float4*)&Ps[r * AS + c] = *(const float4*)&Qg[(size_t)(q0 + r) * HDD + c];
    }
    __syncthreads();

    // ---- Q fragments (register resident for whole kv loop) ----
    uint32_t qf[8][4];
    {
        uint32_t qbase = sptr(Ps) +
            (((w * 16 + (i8 & 1) * 8 + rr) * AS + (i8 >> 1) * 4) << 2);
#pragma unroll
        for (int kk = 0; kk < 8; ++kk) ldsm_x4(qf[kk], qbase + kk * 32);
    }

    // ldmatrix bases reused each tile
    const uint32_t pbase = sptr(Ps) +
        (((w * 16 + (i8 & 1) * 8 + rr) * AS + (i8 >> 1) * 4) << 2);
    uint32_t kaddr[4], vaddr[4];
#pragma unroll
    for (int p = 0; p < 4; ++p) {
        kaddr[p] = sptr(Ks) + ((((2 * p + (i8 >> 1)) * 8 + rr) * AS + (i8 & 1) * 4) << 2);
        vaddr[p] = sptr(Vt) + ((((2 * p + (i8 >> 1)) * 8 + rr) * AS + (i8 & 1) * 4) << 2);
    }

    float oacc[8][4];
#pragma unroll
    for (int nt = 0; nt < 8; ++nt)
#pragma unroll
        for (int i = 0; i < 4; ++i) oacc[nt][i] = 0.0f;
    float mrow[2] = {-1e30f, -1e30f};
    float lrow[2] = {0.0f, 0.0f};

    const int wrow0 = q0 + w * 16;        // first q row of this warp
    const int ktmax = 2 * qt + 1;

    for (int kt = 0; kt <= ktmax; ++kt) {
        __syncthreads();   // previous tile's Ks/Vt/Ps reads done

        // ---- load K tile and transposed V tile ----
#pragma unroll
        for (int i = 0; i < 4; ++i) {
            int idx = tid + 256 * i;
            int r = idx >> 4, c = (idx & 15) << 2;
            *(float4*)&Ks[r * AS + c] = *(const float4*)&Kg[(size_t)(kt * 64 + r) * HDD + c];
            float4 v = *(const float4*)&Vg[(size_t)(kt * 64 + r) * HDD + c];
            Vt[(c + 0) * AS + r] = v.x;
            Vt[(c + 1) * AS + r] = v.y;
            Vt[(c + 2) * AS + r] = v.z;
            Vt[(c + 3) * AS + r] = v.w;
        }
        __syncthreads();

        if (kt * 64 > wrow0 + 15) continue;   // tile fully masked for this warp

        // ---- S = Q K^T (16 x 64 per warp) ----
        float sacc[8][4];
#pragma unroll
        for (int nt = 0; nt < 8; ++nt)
#pragma unroll
            for (int i = 0; i < 4; ++i) sacc[nt][i] = 0.0f;

#pragma unroll
        for (int kk = 0; kk < 8; ++kk) {
            uint32_t bf[4][4];
#pragma unroll
            for (int p = 0; p < 4; ++p) ldsm_x4(bf[p], kaddr[p] + kk * 32);
#pragma unroll
            for (int nt = 0; nt < 8; ++nt)
                mma_tf32(sacc[nt], qf[kk], &bf[nt >> 1][(nt & 1) * 2]);
        }

        // ---- scale + causal mask ----
        const int r0 = wrow0 + g;
        const int r1 = r0 + 8;
        if (kt * 64 + 63 > r0) {   // diagonal region (warp-uniform-ish)
#pragma unroll
            for (int nt = 0; nt < 8; ++nt) {
                const int c0 = kt * 64 + nt * 8 + 2 * t4;
                sacc[nt][0] = (c0     <= r0) ? sacc[nt][0] * 0.125f : -1e30f;
                sacc[nt][1] = (c0 + 1 <= r0) ? sacc[nt][1] * 0.125f : -1e30f;
                sacc[nt][2] = (c0     <= r1) ? sacc[nt][2] * 0.125f : -1e30f;
                sacc[nt][3] = (c0 + 1 <= r1) ? sacc[nt][3] * 0.125f : -1e30f;
            }
        } else {
#pragma unroll
            for (int nt = 0; nt < 8; ++nt)
#pragma unroll
                for (int i = 0; i < 4; ++i) sacc[nt][i] *= 0.125f;
        }

        // ---- online softmax (two rows per thread, reduce over 4 t4 lanes) ----
        float mx0 = -1e30f, mx1 = -1e30f;
#pragma unroll
        for (int nt = 0; nt < 8; ++nt) {
            mx0 = fmaxf(mx0, fmaxf(sacc[nt][0], sacc[nt][1]));
            mx1 = fmaxf(mx1, fmaxf(sacc[nt][2], sacc[nt][3]));
        }
        mx0 = fmaxf(mx0, __shfl_xor_sync(0xffffffffu, mx0, 1));
        mx0 = fmaxf(mx0, __shfl_xor_sync(0xffffffffu, mx0, 2));
        mx1 = fmaxf(mx1, __shfl_xor_sync(0xffffffffu, mx1, 1));
        mx1 = fmaxf(mx1, __shfl_xor_sync(0xffffffffu, mx1, 2));

        const float m0 = fmaxf(mrow[0], mx0);
        const float m1 = fmaxf(mrow[1], mx1);
        float rs0 = 0.0f, rs1 = 0.0f;
#pragma unroll
        for (int nt = 0; nt < 8; ++nt) {
            sacc[nt][0] = __expf(sacc[nt][0] - m0);
            sacc[nt][1] = __expf(sacc[nt][1] - m0);
            sacc[nt][2] = __expf(sacc[nt][2] - m1);
            sacc[nt][3] = __expf(sacc[nt][3] - m1);
            rs0 += sacc[nt][0] + sacc[nt][1];
            rs1 += sacc[nt][2] + sacc[nt][3];
        }
        rs0 += __shfl_xor_sync(0xffffffffu, rs0, 1);
        rs0 += __shfl_xor_sync(0xffffffffu, rs0, 2);
        rs1 += __shfl_xor_sync(0xffffffffu, rs1, 1);
        rs1 += __shfl_xor_sync(0xffffffffu, rs1, 2);

        const float a0 = __expf(mrow[0] - m0);
        const float a1 = __expf(mrow[1] - m1);
        lrow[0] = lrow[0] * a0 + rs0;  mrow[0] = m0;
        lrow[1] = lrow[1] * a1 + rs1;  mrow[1] = m1;
#pragma unroll
        for (int nt = 0; nt < 8; ++nt) {
            oacc[nt][0] *= a0; oacc[nt][1] *= a0;
            oacc[nt][2] *= a1; oacc[nt][3] *= a1;
        }

        // ---- write P tile (own warp's 16 rows only), tf32-rounded ----
        {
            uint32_t* Pu = (uint32_t*)Ps;
            const int lr0 = w * 16 + g;
#pragma unroll
            for (int nt = 0; nt < 8; ++nt) {
                const int co = nt * 8 + 2 * t4;
                uint2 lo = make_uint2(f2tf32(sacc[nt][0]), f2tf32(sacc[nt][1]));
                uint2 hi = make_uint2(f2tf32(sacc[nt][2]), f2tf32(sacc[nt][3]));
                *(uint2*)&Pu[lr0 * AS + co]       = lo;
                *(uint2*)&Pu[(lr0 + 8) * AS + co] = hi;
            }
        }
        __syncwarp();

        // ---- O += P V ----
#pragma unroll
        for (int kk = 0; kk < 8; ++kk) {
            uint32_t pf[4], bf[4][4];
            ldsm_x4(pf, pbase + kk * 32);
#pragma unroll
            for (int p = 0; p < 4; ++p) ldsm_x4(bf[p], vaddr[p] + kk * 32);
#pragma unroll
            for (int nt = 0; nt < 8; ++nt)
                mma_tf32(oacc[nt], pf, &bf[nt >> 1][(nt & 1) * 2]);
        }
    }

    // ---- epilogue ----
    const float inv0 = 1.0f / lrow[0];
    const float inv1 = 1.0f / lrow[1];
    const int row0 = wrow0 + g;
    const int row1 = row0 + 8;
#pragma unroll
    for (int nt = 0; nt < 8; ++nt) {
        const int col = hh * HDD + nt * 8 + 2 * t4;
        float2 lo = make_float2(oacc[nt][0] * inv0, oacc[nt][1] * inv0);
        float2 hi = make_float2(oacc[nt][2] * inv1, oacc[nt][3] * inv1);
        *(float2*)&g_att[((size_t)(bb * TT + row0)) * DD + col] = lo;
        *(float2*)&g_att[((size_t)(bb * TT + row1)) * DD + col] = hi;
    }
}

// ---------------------------------------------------------------------------
extern "C" void kernel_launch(void* const* d_in, const int* in_sizes, int n_in,
                              void* d_out, int out_size)
{
    const float* x  = (const float*)d_in[0];
    const float* wq = (const float*)d_in[1];
    const float* wk = (const float*)d_in[2];
    const float* wv = (const float*)d_in[3];
    const float* wo = (const float*)d_in[4];
    float* out = (float*)d_out;

    const int ATT_SMEM = 256 * AS * (int)sizeof(float);   // 69632 B
    cudaFuncSetAttribute(attn_kernel,
                         cudaFuncAttributeMaxDynamicSharedMemorySize, ATT_SMEM);

    // 1) QKV projections (tensor-core tf32, ldmatrix fragments)
    dim3 gproj(DD / 128, MROWS / 128, 3);   // (8, 32, 3)
    gemm_qkv_kernel<<<gproj, 256>>>(x, wq, wk, wv);

    // 2) causal flash attention (tensor-core tf32)
    dim3 gatt(TT / 128, HH, BB);            // (16, 16, 2)
    attn_kernel<<<gatt, 256, ATT_SMEM>>>();

    // 3) output projection
    dim3 gout(DD / 128, MROWS / 128, 1);    // (8, 32)
    gemm_out_kernel<<<gout, 256>>>(wo, out);
}

// round 6
// speedup vs baseline: 1.0954x; 1.0954x over previous
#include <cuda_runtime.h>
#include <cstdint>

// Problem constants
#define BB   2
#define TT   2048
#define DD   1024
#define HH   16
#define HDD  64
#define MROWS (BB * TT)   // 4096

// Device scratch (no runtime allocation allowed)
__device__ float g_q[BB * HH * TT * HDD];     // [B,H,T,HD], tf32-rounded
__device__ float g_k[BB * HH * TT * HDD];
__device__ float g_v[BB * HH * TT * HDD];
__device__ float g_att[BB * TT * DD];         // [B,T,DIM], full fp32

// ---------------------------------------------------------------------------
// helpers
// ---------------------------------------------------------------------------
__device__ __forceinline__ uint32_t f2tf32(float f) {
    uint32_t r;
    asm("cvt.rna.tf32.f32 %0, %1;" : "=r"(r) : "f"(f));
    return r;
}

__device__ __forceinline__ void mma_tf32(float* c, const uint32_t* a, const uint32_t* b) {
    asm volatile(
        "mma.sync.aligned.m16n8k8.row.col.f32.tf32.tf32.f32 "
        "{%0,%1,%2,%3}, {%4,%5,%6,%7}, {%8,%9}, {%0,%1,%2,%3};"
        : "+f"(c[0]), "+f"(c[1]), "+f"(c[2]), "+f"(c[3])
        : "r"(a[0]), "r"(a[1]), "r"(a[2]), "r"(a[3]), "r"(b[0]), "r"(b[1]));
}

__device__ __forceinline__ uint32_t sptr(const void* p) {
    return (uint32_t)__cvta_generic_to_shared(p);
}

__device__ __forceinline__ void ldsm_x4(uint32_t* r, uint32_t addr) {
    asm volatile("ldmatrix.sync.aligned.m8n8.x4.shared.b16 {%0,%1,%2,%3}, [%4];"
                 : "=r"(r[0]), "=r"(r[1]), "=r"(r[2]), "=r"(r[3]) : "r"(addr));
}

// ---------------------------------------------------------------------------
// Tensor-core NT GEMM: out[m,n] = sum_k A[m,k] * W[n,k]
// CTA 128x128, BK=32, 256 threads, warp tile 32x64.
// Fragments via ldmatrix.x4, staging via packed STS.128.
// 2 CTAs/SM (launch_bounds cap 128 regs) for barrier-bubble hiding.
// QKV==1: scatter into [B,H,T,HD] with tf32 rounding (consumed by attention).
// ---------------------------------------------------------------------------
#define SA 36   // padded stride in words; 36*4 bytes = 16B-aligned rows

template <int QKV>
__device__ __forceinline__ void gemm_tc_body(const float* __restrict__ A,
                                             const float* __restrict__ W,
                                             float* __restrict__ dst)
{
    __shared__ __align__(16) uint32_t As[128 * SA];
    __shared__ __align__(16) uint32_t Bs[128 * SA];

    const int tid    = threadIdx.x;
    const int lane   = tid & 31;
    const int wid    = tid >> 5;
    const int warp_m = wid & 3;
    const int warp_n = wid >> 2;
    const int g      = lane >> 2;
    const int t4     = lane & 3;
    const int i8     = lane >> 3;   // matrix index within ldmatrix.x4
    const int rr     = lane & 7;

    const int m0 = blockIdx.y * 128;
    const int n0 = blockIdx.x * 128;

    const int lr = tid >> 3;
    const int lc = (tid & 7) << 2;

    // ldmatrix base addresses (byte addrs into shared space)
    uint32_t aAddr[2], bAddr[4];
#pragma unroll
    for (int mt = 0; mt < 2; ++mt)
        aAddr[mt] = sptr(As) +
            (((warp_m * 32 + mt * 16 + (i8 & 1) * 8 + rr) * SA + (i8 >> 1) * 4) << 2);
#pragma unroll
    for (int p = 0; p < 4; ++p)
        bAddr[p] = sptr(Bs) +
            (((warp_n * 64 + (2 * p + (i8 >> 1)) * 8 + rr) * SA + (i8 & 1) * 4) << 2);

    float acc[2][8][4];
#pragma unroll
    for (int mt = 0; mt < 2; ++mt)
#pragma unroll
        for (int nt = 0; nt < 8; ++nt)
#pragma unroll
            for (int i = 0; i < 4; ++i) acc[mt][nt][i] = 0.0f;

    float4 areg[4], breg[4];
#pragma unroll
    for (int i = 0; i < 4; ++i) {
        areg[i] = *(const float4*)(A + (size_t)(m0 + lr + 32 * i) * DD + lc);
        breg[i] = *(const float4*)(W + (size_t)(n0 + lr + 32 * i) * DD + lc);
    }

    for (int k0 = 0; k0 < DD; k0 += 32) {
        // stage regs -> smem (tf32 convert), packed 128-bit stores
#pragma unroll
        for (int i = 0; i < 4; ++i) {
            const int r = lr + 32 * i;
            uint4 pa, pb;
            pa.x = f2tf32(areg[i].x); pa.y = f2tf32(areg[i].y);
            pa.z = f2tf32(areg[i].z); pa.w = f2tf32(areg[i].w);
            pb.x = f2tf32(breg[i].x); pb.y = f2tf32(breg[i].y);
            pb.z = f2tf32(breg[i].z); pb.w = f2tf32(breg[i].w);
            *(uint4*)&As[r * SA + lc] = pa;
            *(uint4*)&Bs[r * SA + lc] = pb;
        }
        __syncthreads();

        if (k0 + 32 < DD) {
#pragma unroll
            for (int i = 0; i < 4; ++i) {
                areg[i] = *(const float4*)(A + (size_t)(m0 + lr + 32 * i) * DD + k0 + 32 + lc);
                breg[i] = *(const float4*)(W + (size_t)(n0 + lr + 32 * i) * DD + k0 + 32 + lc);
            }
        }

#pragma unroll
        for (int kk = 0; kk < 4; ++kk) {
            const uint32_t koff = kk * 32;   // 8 words * 4 bytes
            uint32_t af[2][4], bf[4][4];
#pragma unroll
            for (int mt = 0; mt < 2; ++mt) ldsm_x4(af[mt], aAddr[mt] + koff);
#pragma unroll
            for (int p = 0; p < 4; ++p) ldsm_x4(bf[p], bAddr[p] + koff);
#pragma unroll
            for (int mt = 0; mt < 2; ++mt)
#pragma unroll
                for (int nt = 0; nt < 8; ++nt)
                    mma_tf32(acc[mt][nt], af[mt], &bf[nt >> 1][(nt & 1) * 2]);
        }
        __syncthreads();
    }

    // epilogue
#pragma unroll
    for (int mt = 0; mt < 2; ++mt) {
#pragma unroll
        for (int nt = 0; nt < 8; ++nt) {
            const int m1 = m0 + warp_m * 32 + mt * 16 + g;
            const int m2 = m1 + 8;
            const int n  = n0 + warp_n * 64 + nt * 8 + t4 * 2;
            if (QKV) {
                // round to tf32 here so attention can consume raw bits
                float2 lo = make_float2(__uint_as_float(f2tf32(acc[mt][nt][0])),
                                        __uint_as_float(f2tf32(acc[mt][nt][1])));
                float2 hi = make_float2(__uint_as_float(f2tf32(acc[mt][nt][2])),
                                        __uint_as_float(f2tf32(acc[mt][nt][3])));
                const int h = n / HDD, d = n % HDD;
                const int b1 = m1 / TT, t1 = m1 % TT;
                const int b2 = m2 / TT, t2 = m2 % TT;
                *(float2*)(dst + (((size_t)(b1 * HH + h) * TT + t1) * HDD + d)) = lo;
                *(float2*)(dst + (((size_t)(b2 * HH + h) * TT + t2) * HDD + d)) = hi;
            } else {
                float2 lo = make_float2(acc[mt][nt][0], acc[mt][nt][1]);
                float2 hi = make_float2(acc[mt][nt][2], acc[mt][nt][3]);
                *(float2*)(dst + (size_t)m1 * DD + n) = lo;
                *(float2*)(dst + (size_t)m2 * DD + n) = hi;
            }
        }
    }
}

__global__ void __launch_bounds__(256, 2)
gemm_qkv_kernel(const float* __restrict__ x,
                const float* __restrict__ wq,
                const float* __restrict__ wk,
                const float* __restrict__ wv)
{
    const float* W = (blockIdx.z == 0) ? wq : ((blockIdx.z == 1) ? wk : wv);
    float* dst     = (blockIdx.z == 0) ? g_q : ((blockIdx.z == 1) ? g_k : g_v);
    gemm_tc_body<1>(x, W, dst);
}

__global__ void __launch_bounds__(256, 2)
gemm_out_kernel(const float* __restrict__ wo, float* __restrict__ out)
{
    gemm_tc_body<0>(g_att, wo, out);
}

// ---------------------------------------------------------------------------
// Tensor-core flash attention (tf32 MMA, fp32 softmax/accum, causal).
// CTA = (b, h, 128-row q tile), 256 threads = 8 warps, warp = 16 q rows.
// kv tiles of 64. Q fragments register-resident. V transposed in smem.
// 2 CTAs/SM via launch_bounds.
// ---------------------------------------------------------------------------
#define AS 68   // smem stride in words (16B-aligned rows)

__global__ void __launch_bounds__(256, 2) attn_kernel()
{
    extern __shared__ float sm[];
    float* Ps = sm;                 // 128 x AS : Q staging, then P tiles
    float* Ks = sm + 128 * AS;      // 64 x AS
    float* Vt = Ks + 64 * AS;       // 64 x AS  (rows = hd, cols = kv)

    const int tid  = threadIdx.x;
    const int lane = tid & 31;
    const int w    = tid >> 5;       // warp 0..7
    const int g    = lane >> 2;      // 0..7
    const int t4   = lane & 3;       // 0..3
    const int i8   = lane >> 3;
    const int rr   = lane & 7;

    const int qt = blockIdx.x;       // 0..15
    const int hh = blockIdx.y;
    const int bb = blockIdx.z;
    const int q0 = qt * 128;

    const size_t bh_off = (size_t)(bb * HH + hh) * TT * HDD;
    const float* Qg = g_q + bh_off;
    const float* Kg = g_k + bh_off;
    const float* Vg = g_v + bh_off;

    // ---- load Q tile (128 x 64) into Ps ----
#pragma unroll
    for (int i = 0; i < 8; ++i) {
        int idx = tid + 256 * i;
        int r = idx >> 4, c = (idx & 15) << 2;
        *(float4*)&Ps[r * AS + c] = *(const float4*)&Qg[(size_t)(q0 + r) * HDD + c];
    }
    __syncthreads();

    // ---- Q fragments (register resident for whole kv loop) ----
    uint32_t qf[8][4];
    {
        uint32_t qbase = sptr(Ps) +
            (((w * 16 + (i8 & 1) * 8 + rr) * AS + (i8 >> 1) * 4) << 2);
#pragma unroll
        for (int kk = 0; kk < 8; ++kk) ldsm_x4(qf[kk], qbase + kk * 32);
    }

    // ldmatrix bases reused each tile
    const uint32_t pbase = sptr(Ps) +
        (((w * 16 + (i8 & 1) * 8 + rr) * AS + (i8 >> 1) * 4) << 2);
    uint32_t kaddr[4], vaddr[4];
#pragma unroll
    for (int p = 0; p < 4; ++p) {
        kaddr[p] = sptr(Ks) + ((((2 * p + (i8 >> 1)) * 8 + rr) * AS + (i8 & 1) * 4) << 2);
        vaddr[p] = sptr(Vt) + ((((2 * p + (i8 >> 1)) * 8 + rr) * AS + (i8 & 1) * 4) << 2);
    }

    float oacc[8][4];
#pragma unroll
    for (int nt = 0; nt < 8; ++nt)
#pragma unroll
        for (int i = 0; i < 4; ++i) oacc[nt][i] = 0.0f;
    float mrow[2] = {-1e30f, -1e30f};
    float lrow[2] = {0.0f, 0.0f};

    const int wrow0 = q0 + w * 16;        // first q row of this warp
    const int ktmax = 2 * qt + 1;

    for (int kt = 0; kt <= ktmax; ++kt) {
        __syncthreads();   // previous tile's Ks/Vt/Ps reads done

        // ---- load K tile and transposed V tile ----
#pragma unroll
        for (int i = 0; i < 4; ++i) {
            int idx = tid + 256 * i;
            int r = idx >> 4, c = (idx & 15) << 2;
            *(float4*)&Ks[r * AS + c] = *(const float4*)&Kg[(size_t)(kt * 64 + r) * HDD + c];
            float4 v = *(const float4*)&Vg[(size_t)(kt * 64 + r) * HDD + c];
            Vt[(c + 0) * AS + r] = v.x;
            Vt[(c + 1) * AS + r] = v.y;
            Vt[(c + 2) * AS + r] = v.z;
            Vt[(c + 3) * AS + r] = v.w;
        }
        __syncthreads();

        if (kt * 64 > wrow0 + 15) continue;   // tile fully masked for this warp

        // ---- S = Q K^T (16 x 64 per warp) ----
        float sacc[8][4];
#pragma unroll
        for (int nt = 0; nt < 8; ++nt)
#pragma unroll
            for (int i = 0; i < 4; ++i) sacc[nt][i] = 0.0f;

#pragma unroll
        for (int kk = 0; kk < 8; ++kk) {
            uint32_t bf[4][4];
#pragma unroll
            for (int p = 0; p < 4; ++p) ldsm_x4(bf[p], kaddr[p] + kk * 32);
#pragma unroll
            for (int nt = 0; nt < 8; ++nt)
                mma_tf32(sacc[nt], qf[kk], &bf[nt >> 1][(nt & 1) * 2]);
        }

        // ---- scale + causal mask ----
        const int r0 = wrow0 + g;
        const int r1 = r0 + 8;
        if (kt * 64 + 63 > r0) {   // diagonal region
#pragma unroll
            for (int nt = 0; nt < 8; ++nt) {
                const int c0 = kt * 64 + nt * 8 + 2 * t4;
                sacc[nt][0] = (c0     <= r0) ? sacc[nt][0] * 0.125f : -1e30f;
                sacc[nt][1] = (c0 + 1 <= r0) ? sacc[nt][1] * 0.125f : -1e30f;
                sacc[nt][2] = (c0     <= r1) ? sacc[nt][2] * 0.125f : -1e30f;
                sacc[nt][3] = (c0 + 1 <= r1) ? sacc[nt][3] * 0.125f : -1e30f;
            }
        } else {
#pragma unroll
            for (int nt = 0; nt < 8; ++nt)
#pragma unroll
                for (int i = 0; i < 4; ++i) sacc[nt][i] *= 0.125f;
        }

        // ---- online softmax (two rows per thread, reduce over 4 t4 lanes) ----
        float mx0 = -1e30f, mx1 = -1e30f;
#pragma unroll
        for (int nt = 0; nt < 8; ++nt) {
            mx0 = fmaxf(mx0, fmaxf(sacc[nt][0], sacc[nt][1]));
            mx1 = fmaxf(mx1, fmaxf(sacc[nt][2], sacc[nt][3]));
        }
        mx0 = fmaxf(mx0, __shfl_xor_sync(0xffffffffu, mx0, 1));
        mx0 = fmaxf(mx0, __shfl_xor_sync(0xffffffffu, mx0, 2));
        mx1 = fmaxf(mx1, __shfl_xor_sync(0xffffffffu, mx1, 1));
        mx1 = fmaxf(mx1, __shfl_xor_sync(0xffffffffu, mx1, 2));

        const float m0 = fmaxf(mrow[0], mx0);
        const float m1 = fmaxf(mrow[1], mx1);
        float rs0 = 0.0f, rs1 = 0.0f;
#pragma unroll
        for (int nt = 0; nt < 8; ++nt) {
            sacc[nt][0] = __expf(sacc[nt][0] - m0);
            sacc[nt][1] = __expf(sacc[nt][1] - m0);
            sacc[nt][2] = __expf(sacc[nt][2] - m1);
            sacc[nt][3] = __expf(sacc[nt][3] - m1);
            rs0 += sacc[nt][0] + sacc[nt][1];
            rs1 += sacc[nt][2] + sacc[nt][3];
        }
        rs0 += __shfl_xor_sync(0xffffffffu, rs0, 1);
        rs0 += __shfl_xor_sync(0xffffffffu, rs0, 2);
        rs1 += __shfl_xor_sync(0xffffffffu, rs1, 1);
        rs1 += __shfl_xor_sync(0xffffffffu, rs1, 2);

        const float a0 = __expf(mrow[0] - m0);
        const float a1 = __expf(mrow[1] - m1);
        lrow[0] = lrow[0] * a0 + rs0;  mrow[0] = m0;
        lrow[1] = lrow[1] * a1 + rs1;  mrow[1] = m1;
#pragma unroll
        for (int nt = 0; nt < 8; ++nt) {
            oacc[nt][0] *= a0; oacc[nt][1] *= a0;
            oacc[nt][2] *= a1; oacc[nt][3] *= a1;
        }

        // ---- write P tile (own warp's 16 rows only), tf32-rounded ----
        {
            uint32_t* Pu = (uint32_t*)Ps;
            const int lr0 = w * 16 + g;
#pragma unroll
            for (int nt = 0; nt < 8; ++nt) {
                const int co = nt * 8 + 2 * t4;
                uint2 lo = make_uint2(f2tf32(sacc[nt][0]), f2tf32(sacc[nt][1]));
                uint2 hi = make_uint2(f2tf32(sacc[nt][2]), f2tf32(sacc[nt][3]));
                *(uint2*)&Pu[lr0 * AS + co]       = lo;
                *(uint2*)&Pu[(lr0 + 8) * AS + co] = hi;
            }
        }
        __syncwarp();

        // ---- O += P V ----
#pragma unroll
        for (int kk = 0; kk < 8; ++kk) {
            uint32_t pf[4], bf[4][4];
            ldsm_x4(pf, pbase + kk * 32);
#pragma unroll
            for (int p = 0; p < 4; ++p) ldsm_x4(bf[p], vaddr[p] + kk * 32);
#pragma unroll
            for (int nt = 0; nt < 8; ++nt)
                mma_tf32(oacc[nt], pf, &bf[nt >> 1][(nt & 1) * 2]);
        }
    }

    // ---- epilogue ----
    const float inv0 = 1.0f / lrow[0];
    const float inv1 = 1.0f / lrow[1];
    const int row0 = wrow0 + g;
    const int row1 = row0 + 8;
#pragma unroll
    for (int nt = 0; nt < 8; ++nt) {
        const int col = hh * HDD + nt * 8 + 2 * t4;
        float2 lo = make_float2(oacc[nt][0] * inv0, oacc[nt][1] * inv0);
        float2 hi = make_float2(oacc[nt][2] * inv1, oacc[nt][3] * inv1);
        *(float2*)&g_att[((size_t)(bb * TT + row0)) * DD + col] = lo;
        *(float2*)&g_att[((size_t)(bb * TT + row1)) * DD + col] = hi;
    }
}

// ---------------------------------------------------------------------------
extern "C" void kernel_launch(void* const* d_in, const int* in_sizes, int n_in,
                              void* d_out, int out_size)
{
    const float* x  = (const float*)d_in[0];
    const float* wq = (const float*)d_in[1];
    const float* wk = (const float*)d_in[2];
    const float* wv = (const float*)d_in[3];
    const float* wo = (const float*)d_in[4];
    float* out = (float*)d_out;

    const int ATT_SMEM = 256 * AS * (int)sizeof(float);   // 69632 B
    cudaFuncSetAttribute(attn_kernel,
                         cudaFuncAttributeMaxDynamicSharedMemorySize, ATT_SMEM);

    // 1) QKV projections (tensor-core tf32, ldmatrix fragments)
    dim3 gproj(DD / 128, MROWS / 128, 3);   // (8, 32, 3)
    gemm_qkv_kernel<<<gproj, 256>>>(x, wq, wk, wv);

    // 2) causal flash attention (tensor-core tf32)
    dim3 gatt(TT / 128, HH, BB);            // (16, 16, 2)
    attn_kernel<<<gatt, 256, ATT_SMEM>>>();

    // 3) output projection
    dim3 gout(DD / 128, MROWS / 128, 1);    // (8, 32)
    gemm_out_kernel<<<gout, 256>>>(wo, out);
}